// round 15
// baseline (speedup 1.0000x reference)
#include <cuda_runtime.h>
#include <cuda_bf16.h>
#include <cstdint>

#define N_NODES 50000
#define N_EDGES 640000
#define DIM     128
#define LAYERS  3
#define LN_EPS  1e-5f
#define INIT_BLK  ((N_NODES + 255) / 256)    // 196
#define PAD     128                 // padded CSR slots per node

#define BROWS   128                 // rows per MMA block
#define SW      68                  // smem row stride in u32 (conflict-free)
#define WSLOT   (DIM * 64)          // u32 per packed weight matrix (128n x 64kp)
#define SMEM_IN_BYTES (4 * DIM * SW * 4)    // gemm_in: W hi/lo + A hi/lo
#define SMEM_L_BYTES  (6 * DIM * SW * 4)    // layer: W1 hi/lo, W2 hi/lo, A hi/lo

// ---------------- device scratch (no runtime allocation allowed) ------------
__device__ __align__(16) float g_h[N_NODES * DIM];      // fp32 node features
__device__ __align__(16) uint32_t g_mh[N_NODES * 64];   // agg mean, bf16x2 hi
__device__ __align__(16) uint32_t g_ml[N_NODES * 64];   // agg mean, bf16x2 lo
__device__ int g_cur[N_NODES];                 // per-node degree counter
__device__ int g_csr[N_NODES * PAD];           // padded neighbor lists
__device__ int g_is64;
// packed split weights: slot 0=in_w, 1..3=w1[i], 4..6=w2[i]
__device__ __align__(16) uint32_t g_wt_hi[7 * WSLOT];
__device__ __align__(16) uint32_t g_wt_lo[7 * WSLOT];

// ---------------- setup kernels ----------------------------------------------
// blocks 0..INIT_BLK-1 zero degree counters; block INIT_BLK detects edge dtype.
__global__ void k_init(const long long* __restrict__ e) {
    if (blockIdx.x == INIT_BLK) {
        int bad = 0;
        for (int i = threadIdx.x; i < 512; i += 256) {
            long long v = e[i];
            bad |= (v < 0) || (v >= (long long)N_NODES);
        }
        int any = __syncthreads_or(bad);
        if (threadIdx.x == 0) g_is64 = !any;
    } else {
        int i = blockIdx.x * 256 + threadIdx.x;
        if (i < N_NODES) g_cur[i] = 0;
    }
}

// Fused histogram + padded-CSR fill: one pass over edges, no prefix scan.
__global__ void k_fillpad(const void* __restrict__ e) {
    int i = blockIdx.x * blockDim.x + threadIdx.x;
    if (i >= N_EDGES) return;
    int s, d;
    if (g_is64) {
        const long long* p = (const long long*)e;
        s = (int)p[i]; d = (int)p[N_EDGES + i];
    } else {
        const int* p = (const int*)e;
        s = p[i]; d = p[N_EDGES + i];
    }
    int pos = atomicAdd(&g_cur[d], 1);
    if (pos < PAD) g_csr[d * PAD + pos] = s;
}

// -------- weight prep (all 7 slots): W[k][n] f32 -> hi/lo bf16x2 [n][kp] -----
__global__ void k_prep_all(const float* __restrict__ in_w,
                           const float* __restrict__ w1,
                           const float* __restrict__ w2) {
    int gidx = blockIdx.x * blockDim.x + threadIdx.x;   // 0 .. 7*8192-1
    int slot = gidx >> 13;            // /WSLOT
    int idx  = gidx & (WSLOT - 1);
    const float* W = (slot == 0) ? in_w
                   : (slot <= 3) ? w1 + (size_t)(slot - 1) * DIM * DIM
                                 : w2 + (size_t)(slot - 4) * DIM * DIM;
    int n  = idx >> 6;        // 0..127
    int kp = idx & 63;        // 0..63
    float x = W[(2 * kp) * DIM + n];
    float y = W[(2 * kp + 1) * DIM + n];
    __nv_bfloat162 h = __floats2bfloat162_rn(x, y);
    float rx = x - __low2float(h);
    float ry = y - __high2float(h);
    __nv_bfloat162 l = __floats2bfloat162_rn(rx, ry);
    g_wt_hi[gidx] = *reinterpret_cast<uint32_t*>(&h);
    g_wt_lo[gidx] = *reinterpret_cast<uint32_t*>(&l);
}

__device__ __forceinline__ void split_pack(float x, float y,
                                           uint32_t& hi, uint32_t& lo) {
    __nv_bfloat162 h = __floats2bfloat162_rn(x, y);
    float rx = x - __low2float(h);
    float ry = y - __high2float(h);
    __nv_bfloat162 l = __floats2bfloat162_rn(rx, ry);
    hi = *reinterpret_cast<uint32_t*>(&h);
    lo = *reinterpret_cast<uint32_t*>(&l);
}

// ------- aggregation: m[v] = mean of fp32 h rows of neighbors ----------------
// One warp per node; dual accumulators, unroll 4 (measured-best shape).
// Output written PRE-SPLIT as bf16x2 hi/lo words (g_mh/g_ml).
__global__ void __launch_bounds__(256) k_agg() {
    int gid  = blockIdx.x * blockDim.x + threadIdx.x;
    int node = gid >> 5;
    if (node >= N_NODES) return;
    int lane = gid & 31;
    int beg = node * PAD;
    int cnt = g_cur[node];
    cnt = cnt < PAD ? cnt : PAD;
    float4 acc0 = make_float4(0.f, 0.f, 0.f, 0.f);
    float4 acc1 = make_float4(0.f, 0.f, 0.f, 0.f);
    int j = 0;
    #pragma unroll 4
    for (; j + 1 < cnt; j += 2) {
        int s0 = __ldg(&g_csr[beg + j]);
        int s1 = __ldg(&g_csr[beg + j + 1]);
        float4 v0 = *reinterpret_cast<const float4*>(&g_h[(size_t)s0 * DIM + lane * 4]);
        float4 v1 = *reinterpret_cast<const float4*>(&g_h[(size_t)s1 * DIM + lane * 4]);
        acc0.x += v0.x; acc0.y += v0.y; acc0.z += v0.z; acc0.w += v0.w;
        acc1.x += v1.x; acc1.y += v1.y; acc1.z += v1.z; acc1.w += v1.w;
    }
    if (j < cnt) {
        int s0 = __ldg(&g_csr[beg + j]);
        float4 v0 = *reinterpret_cast<const float4*>(&g_h[(size_t)s0 * DIM + lane * 4]);
        acc0.x += v0.x; acc0.y += v0.y; acc0.z += v0.z; acc0.w += v0.w;
    }
    acc0.x += acc1.x; acc0.y += acc1.y; acc0.z += acc1.z; acc0.w += acc1.w;
    float inv = 1.0f / (float)(cnt > 0 ? cnt : 1);
    acc0.x *= inv; acc0.y *= inv; acc0.z *= inv; acc0.w *= inv;
    uint32_t h0, l0, h1, l1;
    split_pack(acc0.x, acc0.y, h0, l0);
    split_pack(acc0.z, acc0.w, h1, l1);
    *reinterpret_cast<uint2*>(&g_mh[(size_t)node * 64 + 2 * lane]) = make_uint2(h0, h1);
    *reinterpret_cast<uint2*>(&g_ml[(size_t)node * 64 + 2 * lane]) = make_uint2(l0, l1);
}

// ---------------- MMA helpers -------------------------------------------------
__device__ __forceinline__ void mma_bf16(float c[4],
        uint32_t a0, uint32_t a1, uint32_t a2, uint32_t a3,
        uint32_t b0, uint32_t b1) {
    asm volatile("mma.sync.aligned.m16n8k16.row.col.f32.bf16.bf16.f32 "
        "{%0,%1,%2,%3}, {%4,%5,%6,%7}, {%8,%9}, {%0,%1,%2,%3};"
        : "+f"(c[0]), "+f"(c[1]), "+f"(c[2]), "+f"(c[3])
        : "r"(a0), "r"(a1), "r"(a2), "r"(a3), "r"(b0), "r"(b1));
}

// 3xBF16 GEMM tile: acc[16][4] += A(warp's 16 rows) x W(128 cols), K=128.
__device__ __forceinline__ void gemm_tile(
        const uint32_t* __restrict__ sAh, const uint32_t* __restrict__ sAl,
        const uint32_t* __restrict__ sWh, const uint32_t* __restrict__ sWl,
        int arow0, int gr, int tc, float acc[16][4]) {
    #pragma unroll 1
    for (int k0 = 0; k0 < 8; k0++) {
        int kp = k0 * 8 + tc;
        uint32_t ah0 = sAh[arow0 + kp];
        uint32_t ah1 = sAh[arow0 + 8 * SW + kp];
        uint32_t ah2 = sAh[arow0 + kp + 4];
        uint32_t ah3 = sAh[arow0 + 8 * SW + kp + 4];
        uint32_t al0 = sAl[arow0 + kp];
        uint32_t al1 = sAl[arow0 + 8 * SW + kp];
        uint32_t al2 = sAl[arow0 + kp + 4];
        uint32_t al3 = sAl[arow0 + 8 * SW + kp + 4];
        #pragma unroll
        for (int nt = 0; nt < 16; nt++) {
            int nrow = (nt * 8 + gr) * SW + kp;
            uint32_t bh0 = sWh[nrow], bh1 = sWh[nrow + 4];
            uint32_t bl0 = sWl[nrow], bl1 = sWl[nrow + 4];
            mma_bf16(acc[nt], ah0, ah1, ah2, ah3, bh0, bh1);
            mma_bf16(acc[nt], ah0, ah1, ah2, ah3, bl0, bl1);
            mma_bf16(acc[nt], al0, al1, al2, al3, bh0, bh1);
        }
    }
}

__device__ __forceinline__ void load_w_smem(uint32_t* sWh, uint32_t* sWl,
                                            int slot, int tid) {
    const float4* srcH = (const float4*)(g_wt_hi + slot * WSLOT);
    const float4* srcL = (const float4*)(g_wt_lo + slot * WSLOT);
    #pragma unroll
    for (int q = 0; q < 8; q++) {
        int idx = tid + q * 256;           // 0..2047 float4s
        int n = idx >> 4, p = idx & 15;
        *reinterpret_cast<float4*>(&sWh[n * SW + p * 4]) = srcH[idx];
        *reinterpret_cast<float4*>(&sWl[n * SW + p * 4]) = srcL[idx];
    }
}

// Load+split a 128x128 f32 A tile from fp32 src into sAh/sAl (gemm_in path).
__device__ __forceinline__ void load_a_smem_f32(uint32_t* sAh, uint32_t* sAl,
                                                const float* __restrict__ src,
                                                int row0, int tid) {
    #pragma unroll
    for (int q = 0; q < 16; q++) {
        int idx = tid + q * 256;           // 0..4095 float4s
        int r = idx >> 5, f4 = idx & 31;
        float4 v = make_float4(0.f, 0.f, 0.f, 0.f);
        if (row0 + r < N_NODES)
            v = *reinterpret_cast<const float4*>(&src[(size_t)(row0 + r) * DIM + f4 * 4]);
        uint32_t h0, l0, h1, l1;
        split_pack(v.x, v.y, h0, l0);
        split_pack(v.z, v.w, h1, l1);
        sAh[r * SW + f4 * 2]     = h0;
        sAh[r * SW + f4 * 2 + 1] = h1;
        sAl[r * SW + f4 * 2]     = l0;
        sAl[r * SW + f4 * 2 + 1] = l1;
    }
}

// Copy a pre-split 128-row A tile from g_mh/g_ml into sAh/sAl (layer path).
__device__ __forceinline__ void load_a_smem_pre(uint32_t* sAh, uint32_t* sAl,
                                                int row0, int tid) {
    #pragma unroll
    for (int q = 0; q < 8; q++) {
        int idx = tid + q * 256;           // 0..2047 uint4
        int r = idx >> 4, c4 = idx & 15;   // row, uint4-column
        uint4 hv = make_uint4(0u, 0u, 0u, 0u);
        uint4 lv = make_uint4(0u, 0u, 0u, 0u);
        if (row0 + r < N_NODES) {
            hv = *reinterpret_cast<const uint4*>(&g_mh[(size_t)(row0 + r) * 64 + c4 * 4]);
            lv = *reinterpret_cast<const uint4*>(&g_ml[(size_t)(row0 + r) * 64 + c4 * 4]);
        }
        *reinterpret_cast<uint4*>(&sAh[r * SW + c4 * 4]) = hv;
        *reinterpret_cast<uint4*>(&sAl[r * SW + c4 * 4]) = lv;
    }
}

// ---------------- input GEMM (tensor core): h = x @ in_w + in_b --------------
__global__ void __launch_bounds__(256, 1) k_gemm_in(
        const float* __restrict__ x, const float* __restrict__ b) {
    extern __shared__ uint32_t smu[];
    uint32_t* sWh = smu;
    uint32_t* sWl = sWh + DIM * SW;
    uint32_t* sAh = sWl + DIM * SW;
    uint32_t* sAl = sAh + DIM * SW;
    int tid = threadIdx.x;
    int row0 = blockIdx.x * BROWS;
    int w = tid >> 5, lane = tid & 31;
    int gr = lane >> 2, tc = lane & 3;
    int arow0 = (w * 16 + gr) * SW;

    load_w_smem(sWh, sWl, 0, tid);
    load_a_smem_f32(sAh, sAl, x, row0, tid);
    __syncthreads();

    float acc[16][4];
    #pragma unroll
    for (int nt = 0; nt < 16; nt++)
        acc[nt][0] = acc[nt][1] = acc[nt][2] = acc[nt][3] = 0.f;

    gemm_tile(sAh, sAl, sWh, sWl, arow0, gr, tc, acc);

    int rowa = row0 + w * 16 + gr;
    int rowb = rowa + 8;
    #pragma unroll
    for (int nt = 0; nt < 16; nt++) {
        float2 bb = ((const float2*)b)[nt * 4 + tc];
        if (rowa < N_NODES) {
            float2 o = make_float2(acc[nt][0] + bb.x, acc[nt][1] + bb.y);
            ((float2*)(g_h + (size_t)rowa * DIM))[nt * 4 + tc] = o;
        }
        if (rowb < N_NODES) {
            float2 o = make_float2(acc[nt][2] + bb.x, acc[nt][3] + bb.y);
            ((float2*)(g_h + (size_t)rowb * DIM))[nt * 4 + tc] = o;
        }
    }
}

// ------- fused layer (tensor core): relu(m@W1+b1)@W2+b2 + h -> LN -----------
// Both weight matrices preloaded at kernel start (204 KB smem).
__global__ void __launch_bounds__(256, 1) k_layer(
        int slot1, const float* __restrict__ b1,
        int slot2, const float* __restrict__ b2,
        const float* __restrict__ gam, const float* __restrict__ bet,
        float* __restrict__ dout /* null -> g_h */) {
    extern __shared__ uint32_t smu[];
    uint32_t* sW1h = smu;
    uint32_t* sW1l = sW1h + DIM * SW;
    uint32_t* sW2h = sW1l + DIM * SW;
    uint32_t* sW2l = sW2h + DIM * SW;
    uint32_t* sAh  = sW2l + DIM * SW;
    uint32_t* sAl  = sAh  + DIM * SW;
    int tid = threadIdx.x;
    int row0 = blockIdx.x * BROWS;
    int w = tid >> 5, lane = tid & 31;
    int gr = lane >> 2, tc = lane & 3;
    int arow0 = (w * 16 + gr) * SW;
    float* out = dout ? dout : g_h;

    load_w_smem(sW1h, sW1l, slot1, tid);
    load_w_smem(sW2h, sW2l, slot2, tid);
    load_a_smem_pre(sAh, sAl, row0, tid);
    __syncthreads();

    // GEMM1
    float acc[16][4];
    #pragma unroll
    for (int nt = 0; nt < 16; nt++)
        acc[nt][0] = acc[nt][1] = acc[nt][2] = acc[nt][3] = 0.f;
    gemm_tile(sAh, sAl, sW1h, sW1l, arow0, gr, tc, acc);

    // bias + relu, write T back into A buffers (own rows only; fragment-packed)
    #pragma unroll
    for (int nt = 0; nt < 16; nt++) {
        float2 bb = ((const float2*)b1)[nt * 4 + tc];
        float v0 = fmaxf(acc[nt][0] + bb.x, 0.f);
        float v1 = fmaxf(acc[nt][1] + bb.y, 0.f);
        float v2 = fmaxf(acc[nt][2] + bb.x, 0.f);
        float v3 = fmaxf(acc[nt][3] + bb.y, 0.f);
        uint32_t h0, l0, h1, l1;
        split_pack(v0, v1, h0, l0);
        split_pack(v2, v3, h1, l1);
        sAh[arow0 + nt * 4 + tc] = h0;
        sAl[arow0 + nt * 4 + tc] = l0;
        sAh[arow0 + 8 * SW + nt * 4 + tc] = h1;
        sAl[arow0 + 8 * SW + nt * 4 + tc] = l1;
    }
    __syncthreads();   // T visible to all warps

    // GEMM2: init with bias + residual (exact fp32 residual)
    int rowa = row0 + w * 16 + gr;
    int rowb = rowa + 8;
    #pragma unroll
    for (int nt = 0; nt < 16; nt++) {
        float2 bb = ((const float2*)b2)[nt * 4 + tc];
        float2 ha = make_float2(0.f, 0.f), hb = make_float2(0.f, 0.f);
        if (rowa < N_NODES) ha = ((const float2*)(g_h + (size_t)rowa * DIM))[nt * 4 + tc];
        if (rowb < N_NODES) hb = ((const float2*)(g_h + (size_t)rowb * DIM))[nt * 4 + tc];
        acc[nt][0] = bb.x + ha.x; acc[nt][1] = bb.y + ha.y;
        acc[nt][2] = bb.x + hb.x; acc[nt][3] = bb.y + hb.y;
    }
    gemm_tile(sAh, sAl, sW2h, sW2l, arow0, gr, tc, acc);

    // LayerNorm: rows rowa (c0,c1) and rowb (c2,c3); reduce over 4-lane quad.
    float sa = 0.f, qa = 0.f, sb = 0.f, qb = 0.f;
    #pragma unroll
    for (int nt = 0; nt < 16; nt++) {
        sa += acc[nt][0] + acc[nt][1];
        qa += acc[nt][0] * acc[nt][0] + acc[nt][1] * acc[nt][1];
        sb += acc[nt][2] + acc[nt][3];
        qb += acc[nt][2] * acc[nt][2] + acc[nt][3] * acc[nt][3];
    }
    #pragma unroll
    for (int o = 1; o < 4; o <<= 1) {
        sa += __shfl_xor_sync(0xffffffffu, sa, o);
        qa += __shfl_xor_sync(0xffffffffu, qa, o);
        sb += __shfl_xor_sync(0xffffffffu, sb, o);
        qb += __shfl_xor_sync(0xffffffffu, qb, o);
    }
    float mua = sa * (1.0f / DIM);
    float vara = qa * (1.0f / DIM) - mua * mua;
    float ra = rsqrtf(vara + LN_EPS);
    float mub = sb * (1.0f / DIM);
    float varb = qb * (1.0f / DIM) - mub * mub;
    float rb = rsqrtf(varb + LN_EPS);

    #pragma unroll
    for (int nt = 0; nt < 16; nt++) {
        float2 gg = ((const float2*)gam)[nt * 4 + tc];
        float2 be = ((const float2*)bet)[nt * 4 + tc];
        if (rowa < N_NODES) {
            float2 o;
            o.x = (acc[nt][0] - mua) * ra * gg.x + be.x;
            o.y = (acc[nt][1] - mua) * ra * gg.y + be.y;
            ((float2*)(out + (size_t)rowa * DIM))[nt * 4 + tc] = o;
        }
        if (rowb < N_NODES) {
            float2 o;
            o.x = (acc[nt][2] - mub) * rb * gg.x + be.x;
            o.y = (acc[nt][3] - mub) * rb * gg.y + be.y;
            ((float2*)(out + (size_t)rowb * DIM))[nt * 4 + tc] = o;
        }
    }
}

// ---------------- launch ------------------------------------------------------
extern "C" void kernel_launch(void* const* d_in, const int* in_sizes, int n_in,
                              void* d_out, int out_size) {
    const float* x    = (const float*)d_in[0];
    const void*  ei   = d_in[1];
    const float* in_w = (const float*)d_in[2];
    const float* in_b = (const float*)d_in[3];
    const float* w1   = (const float*)d_in[4];
    const float* b1   = (const float*)d_in[5];
    const float* w2   = (const float*)d_in[6];
    const float* b2   = (const float*)d_in[7];
    const float* ln_g = (const float*)d_in[8];
    const float* ln_b = (const float*)d_in[9];

    cudaFuncSetAttribute(k_gemm_in, cudaFuncAttributeMaxDynamicSharedMemorySize, SMEM_IN_BYTES);
    cudaFuncSetAttribute(k_layer,   cudaFuncAttributeMaxDynamicSharedMemorySize, SMEM_L_BYTES);

    const int mma_blocks = (N_NODES + BROWS - 1) / BROWS;   // 391

    cudaStream_t s2;
    cudaStreamCreate(&s2);
    cudaEvent_t evFork, evJoin;
    cudaEventCreateWithFlags(&evFork, cudaEventDisableTiming);
    cudaEventCreateWithFlags(&evJoin, cudaEventDisableTiming);

    // Fork point recorded BEFORE the CSR chain; stream B depends only on it.
    cudaEventRecord(evFork, 0);
    cudaStreamWaitEvent(s2, evFork, 0);

    // Stream A (capture stream): padded-CSR build, no prefix scan.
    k_init<<<INIT_BLK + 1, 256>>>((const long long*)ei);
    k_fillpad<<<(N_EDGES + 255) / 256, 256>>>(ei);

    // Stream B: weights + input GEMM (runs concurrently with CSR chain).
    k_prep_all<<<7 * WSLOT / 256, 256, 0, s2>>>(in_w, w1, w2);
    k_gemm_in<<<mma_blocks, 256, SMEM_IN_BYTES, s2>>>(x, in_b);
    cudaEventRecord(evJoin, s2);

    cudaStreamWaitEvent(0, evJoin, 0);

    for (int i = 0; i < LAYERS; i++) {
        float* outp = (i == LAYERS - 1) ? (float*)d_out : nullptr;
        k_agg<<<(N_NODES * 32 + 255) / 256, 256>>>();
        k_layer<<<mma_blocks, 256, SMEM_L_BYTES>>>(
            1 + i, b1 + i * DIM, 4 + i, b2 + i * DIM,
            ln_g + i * DIM, ln_b + i * DIM, outp);
    }

    cudaEventDestroy(evFork);
    cudaEventDestroy(evJoin);
    cudaStreamDestroy(s2);
}

// round 16
// speedup vs baseline: 1.0526x; 1.0526x over previous
#include <cuda_runtime.h>
#include <cuda_bf16.h>
#include <cstdint>

#define N_NODES 50000
#define N_EDGES 640000
#define DIM     128
#define LAYERS  3
#define LN_EPS  1e-5f
#define SCAN_BLK  ((N_NODES + 255) / 256)     // 196

#define BROWS   128                 // rows per MMA block
#define NT      512                 // threads per MMA block (16 warps)
#define SW      68                  // smem row stride in u32 (conflict-free)
#define WSLOT   (DIM * 64)          // u32 per packed weight matrix (128n x 64kp)
#define SMEM_IN_BYTES (4 * DIM * SW * 4)           // gemm_in: W hi/lo + A hi/lo
#define SMEM_L_BYTES  (6 * DIM * SW * 4 + 2048)    // layer: + LN exchange buf

// ---------------- device scratch (no runtime allocation allowed) ------------
__device__ __align__(16) float g_h[N_NODES * DIM];      // fp32 node features
__device__ __align__(16) uint32_t g_mh[N_NODES * 64];   // agg mean, bf16x2 hi
__device__ __align__(16) uint32_t g_ml[N_NODES * 64];   // agg mean, bf16x2 lo
__device__ int g_degi[N_NODES];
__device__ int g_off[N_NODES];     // block-local exclusive prefix
__device__ int g_cur[N_NODES];     // block-local cursor for fill
__device__ int g_csr[N_EDGES];
__device__ int g_bsum[SCAN_BLK];
__device__ int g_bpre[SCAN_BLK];   // per-256-node-block global prefix
__device__ int g_is64;
// packed split weights: slot 0=in_w, 1..3=w1[i], 4..6=w2[i]
__device__ __align__(16) uint32_t g_wt_hi[7 * WSLOT];
__device__ __align__(16) uint32_t g_wt_lo[7 * WSLOT];

// ---------------- setup kernels ----------------------------------------------
__global__ void k_init(const long long* __restrict__ e) {
    if (blockIdx.x == SCAN_BLK) {
        int bad = 0;
        for (int i = threadIdx.x; i < 512; i += 256) {
            long long v = e[i];
            bad |= (v < 0) || (v >= (long long)N_NODES);
        }
        int any = __syncthreads_or(bad);
        if (threadIdx.x == 0) g_is64 = !any;
    } else {
        int i = blockIdx.x * 256 + threadIdx.x;
        if (i < N_NODES) g_degi[i] = 0;
    }
}

__global__ void k_convert(const void* __restrict__ e) {
    int i = blockIdx.x * blockDim.x + threadIdx.x;
    if (i >= N_EDGES) return;
    int d;
    if (g_is64) d = (int)((const long long*)e)[N_EDGES + i];
    else        d = ((const int*)e)[N_EDGES + i];
    atomicAdd(&g_degi[d], 1);
}

__global__ void __launch_bounds__(256) k_scan1() {
    __shared__ int wsum[8];
    int i    = blockIdx.x * 256 + threadIdx.x;
    int lane = threadIdx.x & 31, wid = threadIdx.x >> 5;
    int v = (i < N_NODES) ? g_degi[i] : 0;
    int x = v;
    #pragma unroll
    for (int o = 1; o < 32; o <<= 1) {
        int y = __shfl_up_sync(0xffffffffu, x, o);
        if (lane >= o) x += y;
    }
    if (lane == 31) wsum[wid] = x;
    __syncthreads();
    if (wid == 0 && lane < 8) {
        int s = wsum[lane];
        #pragma unroll
        for (int o = 1; o < 8; o <<= 1) {
            int y = __shfl_up_sync(0xffu, s, o);
            if (lane >= o) s += y;
        }
        wsum[lane] = s;
    }
    __syncthreads();
    int base = (wid > 0) ? wsum[wid - 1] : 0;
    if (i < N_NODES) {
        int loc = base + x - v;
        g_off[i] = loc;
        g_cur[i] = loc;
    }
    if (threadIdx.x == 255) g_bsum[blockIdx.x] = base + x;
}

__global__ void __launch_bounds__(256) k_scan2() {
    __shared__ int wsum[8];
    int tid  = threadIdx.x;
    int lane = tid & 31, wid = tid >> 5;
    int v = (tid < SCAN_BLK) ? g_bsum[tid] : 0;
    int x = v;
    #pragma unroll
    for (int o = 1; o < 32; o <<= 1) {
        int y = __shfl_up_sync(0xffffffffu, x, o);
        if (lane >= o) x += y;
    }
    if (lane == 31) wsum[wid] = x;
    __syncthreads();
    if (wid == 0 && lane < 8) {
        int s = wsum[lane];
        #pragma unroll
        for (int o = 1; o < 8; o <<= 1) {
            int y = __shfl_up_sync(0xffu, s, o);
            if (lane >= o) s += y;
        }
        wsum[lane] = s;
    }
    __syncthreads();
    int base = (wid > 0) ? wsum[wid - 1] : 0;
    if (tid < SCAN_BLK) g_bpre[tid] = base + x - v;
}

__global__ void k_fill(const void* __restrict__ e) {
    int i = blockIdx.x * blockDim.x + threadIdx.x;
    if (i >= N_EDGES) return;
    int s, d;
    if (g_is64) {
        const long long* p = (const long long*)e;
        s = (int)p[i]; d = (int)p[N_EDGES + i];
    } else {
        const int* p = (const int*)e;
        s = p[i]; d = p[N_EDGES + i];
    }
    int pos = atomicAdd(&g_cur[d], 1) + g_bpre[d >> 8];
    g_csr[pos] = s;
}

// -------- weight prep (all 7 slots): W[k][n] f32 -> hi/lo bf16x2 [n][kp] -----
__global__ void k_prep_all(const float* __restrict__ in_w,
                           const float* __restrict__ w1,
                           const float* __restrict__ w2) {
    int gidx = blockIdx.x * blockDim.x + threadIdx.x;   // 0 .. 7*8192-1
    int slot = gidx >> 13;
    int idx  = gidx & (WSLOT - 1);
    const float* W = (slot == 0) ? in_w
                   : (slot <= 3) ? w1 + (size_t)(slot - 1) * DIM * DIM
                                 : w2 + (size_t)(slot - 4) * DIM * DIM;
    int n  = idx >> 6;
    int kp = idx & 63;
    float x = W[(2 * kp) * DIM + n];
    float y = W[(2 * kp + 1) * DIM + n];
    __nv_bfloat162 h = __floats2bfloat162_rn(x, y);
    float rx = x - __low2float(h);
    float ry = y - __high2float(h);
    __nv_bfloat162 l = __floats2bfloat162_rn(rx, ry);
    g_wt_hi[gidx] = *reinterpret_cast<uint32_t*>(&h);
    g_wt_lo[gidx] = *reinterpret_cast<uint32_t*>(&l);
}

__device__ __forceinline__ void split_pack(float x, float y,
                                           uint32_t& hi, uint32_t& lo) {
    __nv_bfloat162 h = __floats2bfloat162_rn(x, y);
    float rx = x - __low2float(h);
    float ry = y - __high2float(h);
    __nv_bfloat162 l = __floats2bfloat162_rn(rx, ry);
    hi = *reinterpret_cast<uint32_t*>(&h);
    lo = *reinterpret_cast<uint32_t*>(&l);
}

// ------- aggregation: m[v] = mean of fp32 h rows of neighbors ----------------
__global__ void __launch_bounds__(256) k_agg() {
    int gid  = blockIdx.x * blockDim.x + threadIdx.x;
    int node = gid >> 5;
    if (node >= N_NODES) return;
    int lane = gid & 31;
    int beg = g_off[node] + g_bpre[node >> 8];
    int cnt = g_degi[node];
    float4 acc0 = make_float4(0.f, 0.f, 0.f, 0.f);
    float4 acc1 = make_float4(0.f, 0.f, 0.f, 0.f);
    int j = 0;
    #pragma unroll 4
    for (; j + 1 < cnt; j += 2) {
        int s0 = __ldg(&g_csr[beg + j]);
        int s1 = __ldg(&g_csr[beg + j + 1]);
        float4 v0 = *reinterpret_cast<const float4*>(&g_h[(size_t)s0 * DIM + lane * 4]);
        float4 v1 = *reinterpret_cast<const float4*>(&g_h[(size_t)s1 * DIM + lane * 4]);
        acc0.x += v0.x; acc0.y += v0.y; acc0.z += v0.z; acc0.w += v0.w;
        acc1.x += v1.x; acc1.y += v1.y; acc1.z += v1.z; acc1.w += v1.w;
    }
    if (j < cnt) {
        int s0 = __ldg(&g_csr[beg + j]);
        float4 v0 = *reinterpret_cast<const float4*>(&g_h[(size_t)s0 * DIM + lane * 4]);
        acc0.x += v0.x; acc0.y += v0.y; acc0.z += v0.z; acc0.w += v0.w;
    }
    acc0.x += acc1.x; acc0.y += acc1.y; acc0.z += acc1.z; acc0.w += acc1.w;
    float inv = 1.0f / (float)(cnt > 0 ? cnt : 1);
    acc0.x *= inv; acc0.y *= inv; acc0.z *= inv; acc0.w *= inv;
    uint32_t h0, l0, h1, l1;
    split_pack(acc0.x, acc0.y, h0, l0);
    split_pack(acc0.z, acc0.w, h1, l1);
    *reinterpret_cast<uint2*>(&g_mh[(size_t)node * 64 + 2 * lane]) = make_uint2(h0, h1);
    *reinterpret_cast<uint2*>(&g_ml[(size_t)node * 64 + 2 * lane]) = make_uint2(l0, l1);
}

// ---------------- MMA helpers -------------------------------------------------
__device__ __forceinline__ void mma_bf16(float c[4],
        uint32_t a0, uint32_t a1, uint32_t a2, uint32_t a3,
        uint32_t b0, uint32_t b1) {
    asm volatile("mma.sync.aligned.m16n8k16.row.col.f32.bf16.bf16.f32 "
        "{%0,%1,%2,%3}, {%4,%5,%6,%7}, {%8,%9}, {%0,%1,%2,%3};"
        : "+f"(c[0]), "+f"(c[1]), "+f"(c[2]), "+f"(c[3])
        : "r"(a0), "r"(a1), "r"(a2), "r"(a3), "r"(b0), "r"(b1));
}

// Half-width 3xBF16 GEMM tile: warp computes its 16 rows x 64 cols (8 nt).
// half selects which 64-column block of W this warp covers.
__device__ __forceinline__ void gemm_tile_h(
        const uint32_t* __restrict__ sAh, const uint32_t* __restrict__ sAl,
        const uint32_t* __restrict__ sWh, const uint32_t* __restrict__ sWl,
        int arow0, int gr, int tc, int half, float acc[8][4]) {
    #pragma unroll 1
    for (int k0 = 0; k0 < 8; k0++) {
        int kp = k0 * 8 + tc;
        uint32_t ah0 = sAh[arow0 + kp];
        uint32_t ah1 = sAh[arow0 + 8 * SW + kp];
        uint32_t ah2 = sAh[arow0 + kp + 4];
        uint32_t ah3 = sAh[arow0 + 8 * SW + kp + 4];
        uint32_t al0 = sAl[arow0 + kp];
        uint32_t al1 = sAl[arow0 + 8 * SW + kp];
        uint32_t al2 = sAl[arow0 + kp + 4];
        uint32_t al3 = sAl[arow0 + 8 * SW + kp + 4];
        #pragma unroll
        for (int nt = 0; nt < 8; nt++) {
            int nrow = ((half * 8 + nt) * 8 + gr) * SW + kp;
            uint32_t bh0 = sWh[nrow], bh1 = sWh[nrow + 4];
            uint32_t bl0 = sWl[nrow], bl1 = sWl[nrow + 4];
            mma_bf16(acc[nt], ah0, ah1, ah2, ah3, bh0, bh1);
            mma_bf16(acc[nt], ah0, ah1, ah2, ah3, bl0, bl1);
            mma_bf16(acc[nt], al0, al1, al2, al3, bh0, bh1);
        }
    }
}

__device__ __forceinline__ void load_w_smem(uint32_t* sWh, uint32_t* sWl,
                                            int slot, int tid) {
    const float4* srcH = (const float4*)(g_wt_hi + slot * WSLOT);
    const float4* srcL = (const float4*)(g_wt_lo + slot * WSLOT);
    #pragma unroll
    for (int q = 0; q < 4; q++) {
        int idx = tid + q * NT;            // 0..2047 float4s
        int n = idx >> 4, p = idx & 15;
        *reinterpret_cast<float4*>(&sWh[n * SW + p * 4]) = srcH[idx];
        *reinterpret_cast<float4*>(&sWl[n * SW + p * 4]) = srcL[idx];
    }
}

// Load+split a 128x128 f32 A tile from fp32 src into sAh/sAl (gemm_in path).
__device__ __forceinline__ void load_a_smem_f32(uint32_t* sAh, uint32_t* sAl,
                                                const float* __restrict__ src,
                                                int row0, int tid) {
    #pragma unroll
    for (int q = 0; q < 8; q++) {
        int idx = tid + q * NT;            // 0..4095 float4s
        int r = idx >> 5, f4 = idx & 31;
        float4 v = make_float4(0.f, 0.f, 0.f, 0.f);
        if (row0 + r < N_NODES)
            v = *reinterpret_cast<const float4*>(&src[(size_t)(row0 + r) * DIM + f4 * 4]);
        uint32_t h0, l0, h1, l1;
        split_pack(v.x, v.y, h0, l0);
        split_pack(v.z, v.w, h1, l1);
        sAh[r * SW + f4 * 2]     = h0;
        sAh[r * SW + f4 * 2 + 1] = h1;
        sAl[r * SW + f4 * 2]     = l0;
        sAl[r * SW + f4 * 2 + 1] = l1;
    }
}

// Copy a pre-split 128-row A tile from g_mh/g_ml into sAh/sAl (layer path).
__device__ __forceinline__ void load_a_smem_pre(uint32_t* sAh, uint32_t* sAl,
                                                int row0, int tid) {
    #pragma unroll
    for (int q = 0; q < 4; q++) {
        int idx = tid + q * NT;            // 0..2047 uint4
        int r = idx >> 4, c4 = idx & 15;
        uint4 hv = make_uint4(0u, 0u, 0u, 0u);
        uint4 lv = make_uint4(0u, 0u, 0u, 0u);
        if (row0 + r < N_NODES) {
            hv = *reinterpret_cast<const uint4*>(&g_mh[(size_t)(row0 + r) * 64 + c4 * 4]);
            lv = *reinterpret_cast<const uint4*>(&g_ml[(size_t)(row0 + r) * 64 + c4 * 4]);
        }
        *reinterpret_cast<uint4*>(&sAh[r * SW + c4 * 4]) = hv;
        *reinterpret_cast<uint4*>(&sAl[r * SW + c4 * 4]) = lv;
    }
}

// ---------------- input GEMM (tensor core): h = x @ in_w + in_b --------------
// 512 threads: warp pair (2wp, 2wp+1) shares 16 rows, each owns a 64-col half.
__global__ void __launch_bounds__(NT, 1) k_gemm_in(
        const float* __restrict__ x, const float* __restrict__ b) {
    extern __shared__ uint32_t smu[];
    uint32_t* sWh = smu;
    uint32_t* sWl = sWh + DIM * SW;
    uint32_t* sAh = sWl + DIM * SW;
    uint32_t* sAl = sAh + DIM * SW;
    int tid = threadIdx.x;
    int row0 = blockIdx.x * BROWS;
    int w = tid >> 5, lane = tid & 31;
    int wp = w >> 1, half = w & 1;
    int gr = lane >> 2, tc = lane & 3;
    int arow0 = (wp * 16 + gr) * SW;

    load_w_smem(sWh, sWl, 0, tid);
    load_a_smem_f32(sAh, sAl, x, row0, tid);
    __syncthreads();

    float acc[8][4];
    #pragma unroll
    for (int nt = 0; nt < 8; nt++)
        acc[nt][0] = acc[nt][1] = acc[nt][2] = acc[nt][3] = 0.f;

    gemm_tile_h(sAh, sAl, sWh, sWl, arow0, gr, tc, half, acc);

    int rowa = row0 + wp * 16 + gr;
    int rowb = rowa + 8;
    #pragma unroll
    for (int nt = 0; nt < 8; nt++) {
        int cp = half * 8 + nt;
        float2 bb = ((const float2*)b)[cp * 4 + tc];
        if (rowa < N_NODES) {
            float2 o = make_float2(acc[nt][0] + bb.x, acc[nt][1] + bb.y);
            ((float2*)(g_h + (size_t)rowa * DIM))[cp * 4 + tc] = o;
        }
        if (rowb < N_NODES) {
            float2 o = make_float2(acc[nt][2] + bb.x, acc[nt][3] + bb.y);
            ((float2*)(g_h + (size_t)rowb * DIM))[cp * 4 + tc] = o;
        }
    }
}

// ------- fused layer (tensor core): relu(m@W1+b1)@W2+b2 + h -> LN -----------
// 512 threads, warp-pair column split; LN combines halves via 2KB smem buf.
__global__ void __launch_bounds__(NT, 1) k_layer(
        int slot1, const float* __restrict__ b1,
        int slot2, const float* __restrict__ b2,
        const float* __restrict__ gam, const float* __restrict__ bet,
        float* __restrict__ dout /* null -> g_h */) {
    extern __shared__ uint32_t smu[];
    uint32_t* sW1h = smu;
    uint32_t* sW1l = sW1h + DIM * SW;
    uint32_t* sW2h = sW1l + DIM * SW;
    uint32_t* sW2l = sW2h + DIM * SW;
    uint32_t* sAh  = sW2l + DIM * SW;
    uint32_t* sAl  = sAh  + DIM * SW;
    float*    sred = (float*)(sAl + DIM * SW);   // [128 rows][2 halves][2]
    int tid = threadIdx.x;
    int row0 = blockIdx.x * BROWS;
    int w = tid >> 5, lane = tid & 31;
    int wp = w >> 1, half = w & 1;
    int gr = lane >> 2, tc = lane & 3;
    int arow0 = (wp * 16 + gr) * SW;
    float* out = dout ? dout : g_h;

    load_w_smem(sW1h, sW1l, slot1, tid);
    load_w_smem(sW2h, sW2l, slot2, tid);
    load_a_smem_pre(sAh, sAl, row0, tid);
    __syncthreads();

    // GEMM1
    float acc[8][4];
    #pragma unroll
    for (int nt = 0; nt < 8; nt++)
        acc[nt][0] = acc[nt][1] = acc[nt][2] = acc[nt][3] = 0.f;
    gemm_tile_h(sAh, sAl, sW1h, sW1l, arow0, gr, tc, half, acc);

    __syncthreads();   // both halves of a warp pair read shared A rows

    // bias + relu, write T back into A buffers (warp's col half, rows shared)
    #pragma unroll
    for (int nt = 0; nt < 8; nt++) {
        int cp = half * 8 + nt;
        float2 bb = ((const float2*)b1)[cp * 4 + tc];
        float v0 = fmaxf(acc[nt][0] + bb.x, 0.f);
        float v1 = fmaxf(acc[nt][1] + bb.y, 0.f);
        float v2 = fmaxf(acc[nt][2] + bb.x, 0.f);
        float v3 = fmaxf(acc[nt][3] + bb.y, 0.f);
        uint32_t h0, l0, h1, l1;
        split_pack(v0, v1, h0, l0);
        split_pack(v2, v3, h1, l1);
        sAh[arow0 + cp * 4 + tc] = h0;
        sAl[arow0 + cp * 4 + tc] = l0;
        sAh[arow0 + 8 * SW + cp * 4 + tc] = h1;
        sAl[arow0 + 8 * SW + cp * 4 + tc] = l1;
    }
    __syncthreads();   // T visible to all warps

    // GEMM2: init with bias + residual (exact fp32 residual)
    int rowa = row0 + wp * 16 + gr;
    int rowb = rowa + 8;
    #pragma unroll
    for (int nt = 0; nt < 8; nt++) {
        int cp = half * 8 + nt;
        float2 bb = ((const float2*)b2)[cp * 4 + tc];
        float2 ha = make_float2(0.f, 0.f), hb = make_float2(0.f, 0.f);
        if (rowa < N_NODES) ha = ((const float2*)(g_h + (size_t)rowa * DIM))[cp * 4 + tc];
        if (rowb < N_NODES) hb = ((const float2*)(g_h + (size_t)rowb * DIM))[cp * 4 + tc];
        acc[nt][0] = bb.x + ha.x; acc[nt][1] = bb.y + ha.y;
        acc[nt][2] = bb.x + hb.x; acc[nt][3] = bb.y + hb.y;
    }
    gemm_tile_h(sAh, sAl, sW2h, sW2l, arow0, gr, tc, half, acc);

    // LayerNorm: quad-reduce within warp (64 cols), then combine halves in smem.
    float sa = 0.f, qa = 0.f, sb = 0.f, qb = 0.f;
    #pragma unroll
    for (int nt = 0; nt < 8; nt++) {
        sa += acc[nt][0] + acc[nt][1];
        qa += acc[nt][0] * acc[nt][0] + acc[nt][1] * acc[nt][1];
        sb += acc[nt][2] + acc[nt][3];
        qb += acc[nt][2] * acc[nt][2] + acc[nt][3] * acc[nt][3];
    }
    #pragma unroll
    for (int o = 1; o < 4; o <<= 1) {
        sa += __shfl_xor_sync(0xffffffffu, sa, o);
        qa += __shfl_xor_sync(0xffffffffu, qa, o);
        sb += __shfl_xor_sync(0xffffffffu, sb, o);
        qb += __shfl_xor_sync(0xffffffffu, qb, o);
    }
    int ra = wp * 16 + gr;       // tile-row of rowa
    int rb = ra + 8;             // tile-row of rowb
    __syncthreads();             // all warps done with GEMM2 smem reads
    if (tc == 0) {
        sred[ra * 4 + half * 2 + 0] = sa;
        sred[ra * 4 + half * 2 + 1] = qa;
        sred[rb * 4 + half * 2 + 0] = sb;
        sred[rb * 4 + half * 2 + 1] = qb;
    }
    __syncthreads();
    float saT = sred[ra * 4 + 0] + sred[ra * 4 + 2];
    float qaT = sred[ra * 4 + 1] + sred[ra * 4 + 3];
    float sbT = sred[rb * 4 + 0] + sred[rb * 4 + 2];
    float qbT = sred[rb * 4 + 1] + sred[rb * 4 + 3];
    float mua = saT * (1.0f / DIM);
    float vara = qaT * (1.0f / DIM) - mua * mua;
    float rsa = rsqrtf(vara + LN_EPS);
    float mub = sbT * (1.0f / DIM);
    float varb = qbT * (1.0f / DIM) - mub * mub;
    float rsb = rsqrtf(varb + LN_EPS);

    #pragma unroll
    for (int nt = 0; nt < 8; nt++) {
        int cp = half * 8 + nt;
        float2 gg = ((const float2*)gam)[cp * 4 + tc];
        float2 be = ((const float2*)bet)[cp * 4 + tc];
        if (rowa < N_NODES) {
            float2 o;
            o.x = (acc[nt][0] - mua) * rsa * gg.x + be.x;
            o.y = (acc[nt][1] - mua) * rsa * gg.y + be.y;
            ((float2*)(out + (size_t)rowa * DIM))[cp * 4 + tc] = o;
        }
        if (rowb < N_NODES) {
            float2 o;
            o.x = (acc[nt][2] - mub) * rsb * gg.x + be.x;
            o.y = (acc[nt][3] - mub) * rsb * gg.y + be.y;
            ((float2*)(out + (size_t)rowb * DIM))[cp * 4 + tc] = o;
        }
    }
}

// ---------------- launch ------------------------------------------------------
extern "C" void kernel_launch(void* const* d_in, const int* in_sizes, int n_in,
                              void* d_out, int out_size) {
    const float* x    = (const float*)d_in[0];
    const void*  ei   = d_in[1];
    const float* in_w = (const float*)d_in[2];
    const float* in_b = (const float*)d_in[3];
    const float* w1   = (const float*)d_in[4];
    const float* b1   = (const float*)d_in[5];
    const float* w2   = (const float*)d_in[6];
    const float* b2   = (const float*)d_in[7];
    const float* ln_g = (const float*)d_in[8];
    const float* ln_b = (const float*)d_in[9];

    cudaFuncSetAttribute(k_gemm_in, cudaFuncAttributeMaxDynamicSharedMemorySize, SMEM_IN_BYTES);
    cudaFuncSetAttribute(k_layer,   cudaFuncAttributeMaxDynamicSharedMemorySize, SMEM_L_BYTES);

    const int mma_blocks = (N_NODES + BROWS - 1) / BROWS;   // 391

    cudaStream_t s2;
    cudaStreamCreate(&s2);
    cudaEvent_t evFork, evJoin;
    cudaEventCreateWithFlags(&evFork, cudaEventDisableTiming);
    cudaEventCreateWithFlags(&evJoin, cudaEventDisableTiming);

    cudaEventRecord(evFork, 0);
    cudaStreamWaitEvent(s2, evFork, 0);

    // Stream A (capture stream): CSR build.
    k_init<<<SCAN_BLK + 1, 256>>>((const long long*)ei);
    k_convert<<<(N_EDGES + 255) / 256, 256>>>(ei);
    k_scan1<<<SCAN_BLK, 256>>>();
    k_scan2<<<1, 256>>>();
    k_fill<<<(N_EDGES + 255) / 256, 256>>>(ei);

    // Stream B: weights + input GEMM (runs concurrently with CSR chain).
    k_prep_all<<<7 * WSLOT / 256, 256, 0, s2>>>(in_w, w1, w2);
    k_gemm_in<<<mma_blocks, NT, SMEM_IN_BYTES, s2>>>(x, in_b);
    cudaEventRecord(evJoin, s2);

    cudaStreamWaitEvent(0, evJoin, 0);

    for (int i = 0; i < LAYERS; i++) {
        float* outp = (i == LAYERS - 1) ? (float*)d_out : nullptr;
        k_agg<<<(N_NODES * 32 + 255) / 256, 256>>>();
        k_layer<<<mma_blocks, NT, SMEM_L_BYTES>>>(
            1 + i, b1 + i * DIM, 4 + i, b2 + i * DIM,
            ln_g + i * DIM, ln_b + i * DIM, outp);
    }

    cudaEventDestroy(evFork);
    cudaEventDestroy(evJoin);
    cudaStreamDestroy(s2);
}